// round 15
// baseline (speedup 1.0000x reference)
#include <cuda_runtime.h>
#include <cuda_fp16.h>
#include <cstdint>

#define HW 65536       // 256*256
#define CCH 256
#define NB 2

// ---------------------------------------------------------------------------
// Scratch (device globals — no allocations allowed)
// ---------------------------------------------------------------------------
__device__ __half g_qkv[(size_t)NB * 768 * HW];   // fp16, window layout [win][part][head][d][tok]
__device__ __half g_att[(size_t)NB * CCH * HW];   // fp16 attention+residual, channel-major
__device__ __half g_xh [(size_t)NB * CCH * HW];
__device__ __half g_yh [(size_t)NB * CCH * HW];
__device__ __half g_wq [768 * 256];
__device__ __half g_wp [256 * 256];

// ---------------------------------------------------------------------------
// PTX helpers (plain sm_80+ PTX)
// ---------------------------------------------------------------------------
__device__ __forceinline__ uint32_t smem_to_u32(const void* p) {
    uint32_t a;
    asm("{ .reg .u64 t; cvta.to.shared.u64 t, %1; cvt.u32.u64 %0, t; }" : "=r"(a) : "l"(p));
    return a;
}
__device__ __forceinline__ void ldsm_x4(uint32_t (&r)[4], uint32_t addr) {
    asm volatile("ldmatrix.sync.aligned.m8n8.x4.shared.b16 {%0,%1,%2,%3}, [%4];"
                 : "=r"(r[0]), "=r"(r[1]), "=r"(r[2]), "=r"(r[3]) : "r"(addr));
}
__device__ __forceinline__ void ldsm_x4_t(uint32_t (&r)[4], uint32_t addr) {
    asm volatile("ldmatrix.sync.aligned.m8n8.x4.trans.shared.b16 {%0,%1,%2,%3}, [%4];"
                 : "=r"(r[0]), "=r"(r[1]), "=r"(r[2]), "=r"(r[3]) : "r"(addr));
}
__device__ __forceinline__ void ldsm_x2_t(uint32_t (&r)[2], uint32_t addr) {
    asm volatile("ldmatrix.sync.aligned.m8n8.x2.trans.shared.b16 {%0,%1}, [%2];"
                 : "=r"(r[0]), "=r"(r[1]) : "r"(addr));
}
__device__ __forceinline__ void mma_f16(float (&c)[4], const uint32_t (&a)[4],
                                        const uint32_t* b) {
    asm volatile("mma.sync.aligned.m16n8k16.row.col.f32.f16.f16.f32 "
                 "{%0,%1,%2,%3}, {%4,%5,%6,%7}, {%8,%9}, {%0,%1,%2,%3};"
                 : "+f"(c[0]), "+f"(c[1]), "+f"(c[2]), "+f"(c[3])
                 : "r"(a[0]), "r"(a[1]), "r"(a[2]), "r"(a[3]), "r"(b[0]), "r"(b[1]));
}
__device__ __forceinline__ void cp_async16(uint32_t sm, const void* g) {
    asm volatile("cp.async.cg.shared.global [%0], [%1], 16;" :: "r"(sm), "l"(g));
}
__device__ __forceinline__ uint32_t pack_f16x2(float lo, float hi) {
    uint32_t r;
    asm("cvt.rn.f16x2.f32 %0, %1, %2;" : "=r"(r) : "f"(hi), "f"(lo));
    return r;
}

// ---------------------------------------------------------------------------
// fp32 -> fp16 convert (vectorized by 4)
// ---------------------------------------------------------------------------
__global__ __launch_bounds__(256) void cvt_f16(const float* __restrict__ in,
                                               __half* __restrict__ out, size_t n4) {
    size_t i = (size_t)blockIdx.x * blockDim.x + threadIdx.x;
    if (i >= n4) return;
    float4 v = reinterpret_cast<const float4*>(in)[i];
    reinterpret_cast<__half2*>(out)[i * 2]     = __floats2half2_rn(v.x, v.y);
    reinterpret_cast<__half2*>(out)[i * 2 + 1] = __floats2half2_rn(v.z, v.w);
}

// ---------------------------------------------------------------------------
// cp.async pipelined fp16 tensor-core GEMM with smem-resident A (R13 config).
// BM=128, BN=128, BK=32; 256 threads (8 warps, 2x4), warp tile 64x32.
// MODE 0: write fp32 channel-major.  MODE 1: write fp16 window layout.
// ---------------------------------------------------------------------------
#define SA_STRIDE 528      // 256 halfs (512B) + 16B pad  (132 words ≡ 4 mod 32)
#define SB_STRIDE 272      // 128 halfs (256B) padded
#define SA_OFF 0
#define SB_OFF 67584       // 128*528
#define BSTAGE 8704        // 32*272
#define SM_TOT (67584 + 4 * BSTAGE)   // 102400

template<int MODE>
__global__ __launch_bounds__(256, 2) void mma_gemm(const __half* __restrict__ Wm,
                                                   const __half* __restrict__ X,
                                                   void* __restrict__ Yv, int Mtot) {
    extern __shared__ __align__(128) char smem[];
    const int tid  = threadIdx.x;
    const int wid  = tid >> 5;
    const int lane = tid & 31;
    const int g    = lane >> 2;
    const int t4   = lane & 3;

    const int oBase = blockIdx.x * 128;
    const int sBase = blockIdx.y * 128;
    const int b     = blockIdx.z;
    const __half* Xb = X + (size_t)b * CCH * HW;

    const int wm = (wid >> 2) * 64;
    const int wn = (wid & 3) * 32;
    const uint32_t sb = smem_to_u32(smem);

    const int bk_ = tid >> 4, bq_ = tid & 15;

    float acc[4][4][4];
    #pragma unroll
    for (int mi = 0; mi < 4; mi++)
        #pragma unroll
        for (int ni = 0; ni < 4; ni++)
            #pragma unroll
            for (int q = 0; q < 4; q++) acc[mi][ni][q] = 0.f;

    // ---- prologue: stage the FULL A slab (128 x 256 halfs) once ----
    {
        #pragma unroll
        for (int p = 0; p < 16; p++) {
            int i = tid + p * 256;           // 0..4095
            int r = i >> 5, c = i & 31;
            cp_async16(sb + SA_OFF + r * SA_STRIDE + c * 16,
                       Wm + (size_t)(oBase + r) * 256 + c * 8);
        }
        asm volatile("cp.async.commit_group;");
    }

    auto issueB = [&](int chunk) {
        const int kc = chunk * 32;
        const uint32_t st = sb + SB_OFF + (chunk & 3) * BSTAGE;
        #pragma unroll
        for (int p = 0; p < 2; p++) {
            int k = bk_ + p * 16;
            cp_async16(st + k * SB_STRIDE + bq_ * 16,
                       Xb + (size_t)(kc + k) * HW + sBase + bq_ * 8);
        }
        asm volatile("cp.async.commit_group;");
    };

    const int bquad = lane >> 3, bj = lane & 7;
    const int bkrow = (bquad & 1) * 8 + bj;
    const int bcol8 = (bquad >> 1) * 8;

    issueB(0); issueB(1); issueB(2);
    #pragma unroll
    for (int chunk = 0; chunk < 8; chunk++) {
        if (chunk < 6) {
            asm volatile("cp.async.wait_group 2;");
        } else if (chunk == 6) {
            asm volatile("cp.async.wait_group 1;");
        } else {
            asm volatile("cp.async.wait_group 0;");
        }
        __syncthreads();
        if (chunk < 5) issueB(chunk + 3);

        const uint32_t smb = sb + SB_OFF + (chunk & 3) * BSTAGE;
        const int ar    = wm + (lane & 15);
        const int acolq = (lane >> 4) * 8;

        #pragma unroll
        for (int ks = 0; ks < 2; ks++) {
            uint32_t a[4][4];
            const int acol = chunk * 32 + ks * 16 + acolq;
            #pragma unroll
            for (int mi = 0; mi < 4; mi++)
                ldsm_x4(a[mi], sb + SA_OFF + (ar + mi * 16) * SA_STRIDE + acol * 2);
            uint32_t bfr[2][4];
            #pragma unroll
            for (int ni2 = 0; ni2 < 2; ni2++)
                ldsm_x4_t(bfr[ni2], smb + (ks * 16 + bkrow) * SB_STRIDE
                                     + (wn + ni2 * 16 + bcol8) * 2);
            #pragma unroll
            for (int mi = 0; mi < 4; mi++)
                #pragma unroll
                for (int ni = 0; ni < 4; ni++)
                    mma_f16(acc[mi][ni], a[mi], &bfr[ni >> 1][(ni & 1) * 2]);
        }
    }

    if (MODE == 0) {
        float* Yb = (float*)Yv + (size_t)b * Mtot * HW;
        #pragma unroll
        for (int mi = 0; mi < 4; mi++) {
            #pragma unroll
            for (int ni = 0; ni < 4; ni++) {
                float* dst0 = Yb + (size_t)(oBase + wm + mi * 16 + g) * HW
                                 + sBase + wn + ni * 8 + t4 * 2;
                *reinterpret_cast<float2*>(dst0) = make_float2(acc[mi][ni][0], acc[mi][ni][1]);
                *reinterpret_cast<float2*>(dst0 + 8 * HW) = make_float2(acc[mi][ni][2], acc[mi][ni][3]);
            }
        }
    } else {
        __half* U = (__half*)Yv;
        #pragma unroll
        for (int mi = 0; mi < 4; mi++) {
            #pragma unroll
            for (int ni = 0; ni < 4; ni++) {
                const int o0   = oBase + wm + mi * 16 + g;
                const int part = o0 >> 8;
                const int head = (o0 >> 4) & 15;
                const int dd   = o0 & 15;
                const int s0   = sBase + wn + ni * 8 + t4 * 2;
                const int y    = s0 >> 8, xx = s0 & 255;
                const int win  = b * 1024 + (y >> 3) * 32 + (xx >> 3);
                const int tok  = (y & 7) * 8 + (xx & 7);
                const size_t base = ((size_t)(win * 3 + part) * 16 + head) * 1024 + tok;
                *reinterpret_cast<__half2*>(U + base + (size_t)dd * 64) =
                    __floats2half2_rn(acc[mi][ni][0], acc[mi][ni][1]);
                *reinterpret_cast<__half2*>(U + base + (size_t)(dd + 8) * 64) =
                    __floats2half2_rn(acc[mi][ni][2], acc[mi][ni][3]);
            }
        }
    }
}

// ---------------------------------------------------------------------------
// Tensor-core window attention (fp16), smem-staged (R9 config).
// ---------------------------------------------------------------------------
#define QROW 144
#define SEGSZ 2304

__global__ __launch_bounds__(256) void attn_mma(const __half* __restrict__ qkvH,
                                                const __half* __restrict__ xh,
                                                const float* __restrict__ bias_table,
                                                __half* __restrict__ att) {
    const int win = blockIdx.x;
    const int hg  = blockIdx.y;
    const int tid = threadIdx.x;
    const int w    = tid >> 5;
    const int lane = tid & 31;
    const int hl   = w >> 1;
    const int wsub = w & 1;
    const int g = lane >> 2, t = lane & 3;

    __shared__ __align__(16) char qs[12 * SEGSZ];
    __shared__ float  bs4[4][225];
    __shared__ __half obuf[4][16][80];

    const uint32_t qs_b = smem_to_u32(qs);

    #pragma unroll
    for (int p = 0; p < 6; p++) {
        int i = tid + p * 256;
        int seg = i >> 7;
        int c   = i & 127;
        int part = seg >> 2, hl2 = seg & 3;
        const __half* src = qkvH + ((size_t)(win * 3 + part) * 16 + hg * 4 + hl2) * 1024 + c * 8;
        cp_async16(qs_b + seg * SEGSZ + (c >> 3) * QROW + (c & 7) * 16, src);
    }
    asm volatile("cp.async.commit_group;");
    for (int i = tid; i < 900; i += 256)
        bs4[i / 225][i % 225] = bias_table[(i % 225) * 16 + hg * 4 + i / 225];
    asm volatile("cp.async.wait_group 0;");
    __syncthreads();

    const uint32_t qbase = qs_b + hl * SEGSZ;
    const uint32_t kbase = qs_b + (4 + hl) * SEGSZ;
    const uint32_t* Vs32 = (const uint32_t*)(qs + (8 + hl) * SEGSZ);

    uint32_t afr[2][4];
    {
        const int quad = lane >> 3, j = lane & 7;
        const int krow = ((quad >= 2) ? 8 : 0) + j;
        const int mcolo = (quad & 1) ? 16 : 0;
        #pragma unroll
        for (int mi = 0; mi < 2; mi++) {
            const int m0 = wsub * 32 + mi * 16;
            ldsm_x4_t(afr[mi], qbase + krow * QROW + m0 * 2 + mcolo);
        }
    }
    uint32_t bfr[8][2];
    #pragma unroll
    for (int ni = 0; ni < 8; ni++)
        ldsm_x2_t(bfr[ni], kbase + (lane & 15) * QROW + ni * 16);

    float C[2][8][4];
    #pragma unroll
    for (int mi = 0; mi < 2; mi++)
        #pragma unroll
        for (int ni = 0; ni < 8; ni++) {
            C[mi][ni][0] = C[mi][ni][1] = C[mi][ni][2] = C[mi][ni][3] = 0.f;
            mma_f16(C[mi][ni], afr[mi], bfr[ni]);
        }

    #pragma unroll
    for (int mi = 0; mi < 2; mi++) {
        const int yl0 = wsub * 4 + mi * 2;
        float m0 = -1e30f, m1 = -1e30f;
        #pragma unroll
        for (int ni = 0; ni < 8; ni++) {
            const int cb0 = g - t * 2 + 7;
            C[mi][ni][0] = C[mi][ni][0] * 0.25f + bs4[hl][(yl0 - ni + 7) * 15 + cb0];
            C[mi][ni][1] = C[mi][ni][1] * 0.25f + bs4[hl][(yl0 - ni + 7) * 15 + cb0 - 1];
            C[mi][ni][2] = C[mi][ni][2] * 0.25f + bs4[hl][(yl0 + 1 - ni + 7) * 15 + cb0];
            C[mi][ni][3] = C[mi][ni][3] * 0.25f + bs4[hl][(yl0 + 1 - ni + 7) * 15 + cb0 - 1];
            m0 = fmaxf(m0, fmaxf(C[mi][ni][0], C[mi][ni][1]));
            m1 = fmaxf(m1, fmaxf(C[mi][ni][2], C[mi][ni][3]));
        }
        m0 = fmaxf(m0, __shfl_xor_sync(0xffffffffu, m0, 1));
        m0 = fmaxf(m0, __shfl_xor_sync(0xffffffffu, m0, 2));
        m1 = fmaxf(m1, __shfl_xor_sync(0xffffffffu, m1, 1));
        m1 = fmaxf(m1, __shfl_xor_sync(0xffffffffu, m1, 2));
        float s0 = 0.f, s1 = 0.f;
        #pragma unroll
        for (int ni = 0; ni < 8; ni++) {
            C[mi][ni][0] = __expf(C[mi][ni][0] - m0);
            C[mi][ni][1] = __expf(C[mi][ni][1] - m0);
            C[mi][ni][2] = __expf(C[mi][ni][2] - m1);
            C[mi][ni][3] = __expf(C[mi][ni][3] - m1);
            s0 += C[mi][ni][0] + C[mi][ni][1];
            s1 += C[mi][ni][2] + C[mi][ni][3];
        }
        s0 += __shfl_xor_sync(0xffffffffu, s0, 1);
        s0 += __shfl_xor_sync(0xffffffffu, s0, 2);
        s1 += __shfl_xor_sync(0xffffffffu, s1, 1);
        s1 += __shfl_xor_sync(0xffffffffu, s1, 2);
        const float iv0 = 1.f / s0, iv1 = 1.f / s1;
        #pragma unroll
        for (int ni = 0; ni < 8; ni++) {
            C[mi][ni][0] *= iv0; C[mi][ni][1] *= iv0;
            C[mi][ni][2] *= iv1; C[mi][ni][3] *= iv1;
        }
    }

    float O[2][2][4];
    #pragma unroll
    for (int mi = 0; mi < 2; mi++)
        #pragma unroll
        for (int nd = 0; nd < 2; nd++)
            O[mi][nd][0] = O[mi][nd][1] = O[mi][nd][2] = O[mi][nd][3] = 0.f;

    #pragma unroll
    for (int kk = 0; kk < 4; kk++) {
        uint32_t vfr[2][2];
        #pragma unroll
        for (int nd = 0; nd < 2; nd++)
            #pragma unroll
            for (int r = 0; r < 2; r++)
                vfr[nd][r] = Vs32[(nd * 8 + g) * 36 + kk * 8 + t + r * 4];
        #pragma unroll
        for (int mi = 0; mi < 2; mi++) {
            uint32_t pfr[4];
            #pragma unroll
            for (int r = 0; r < 4; r++) {
                const int ni = 2 * kk + (r >> 1);
                pfr[r] = pack_f16x2(C[mi][ni][(r & 1) * 2], C[mi][ni][(r & 1) * 2 + 1]);
            }
            #pragma unroll
            for (int nd = 0; nd < 2; nd++)
                mma_f16(O[mi][nd], pfr, vfr[nd]);
        }
    }

    #pragma unroll
    for (int mi = 0; mi < 2; mi++) {
        const int m = wsub * 32 + mi * 16 + g;
        #pragma unroll
        for (int nd = 0; nd < 2; nd++) {
            const int d0 = nd * 8 + t * 2;
            obuf[hl][d0    ][m]     = __float2half(O[mi][nd][0]);
            obuf[hl][d0 + 1][m]     = __float2half(O[mi][nd][1]);
            obuf[hl][d0    ][m + 8] = __float2half(O[mi][nd][2]);
            obuf[hl][d0 + 1][m + 8] = __float2half(O[mi][nd][3]);
        }
    }
    __syncthreads();

    const int bW = win >> 10, loc = win & 1023;
    const int wy = loc >> 5, wx = loc & 31;
    #pragma unroll
    for (int p = 0; p < 2; p++) {
        const int i   = tid + p * 256;
        const int hl2 = i >> 7;
        const int d   = (i >> 3) & 15;
        const int row = i & 7;
        const size_t off = ((size_t)bW * 256 + (hg * 4 + hl2) * 16 + d) * HW
                         + (size_t)(wy * 8 + row) * 256 + wx * 8;
        uint4 xv = *reinterpret_cast<const uint4*>(xh + off);
        const __half2* ob = reinterpret_cast<const __half2*>(&obuf[hl2][d][row * 8]);
        __half2* xp = reinterpret_cast<__half2*>(&xv);
        uint4 res;
        __half2* rp = reinterpret_cast<__half2*>(&res);
        #pragma unroll
        for (int q = 0; q < 4; q++) rp[q] = __hadd2(ob[q], xp[q]);
        *reinterpret_cast<uint4*>(att + off) = res;
    }
}

// ---------------------------------------------------------------------------
// reflect-pad -> depthwise 3x3 -> BN -> fp16, smem-halo tiled.
// Block: 256 threads, tile 128(x) x 8(y). Halo 130 x 10 staged in smem.
// grid: (2, 32, NB*CCH).
// ---------------------------------------------------------------------------
__global__ __launch_bounds__(256) void dwbn_kernel(const __half* __restrict__ att,
                                                   const float* __restrict__ dw_w,
                                                   const float* __restrict__ gamma,
                                                   const float* __restrict__ beta,
                                                   const float* __restrict__ mean,
                                                   const float* __restrict__ var,
                                                   __half* __restrict__ yh) {
    const int c  = blockIdx.z & 255;
    const int b  = blockIdx.z >> 8;
    const int x0 = blockIdx.x * 128;
    const int y0 = blockIdx.y * 8;
    const int tid = threadIdx.x;

    __shared__ __half sm[10][132];

    const __half* in = att + ((size_t)b * CCH + c) * HW;

    // ---- stage halo tile: rows y0-1..y0+8, cols x0-1..x0+128 ----
    for (int i = tid; i < 1300; i += 256) {
        const int r = i / 130, cc = i % 130;
        int gy = y0 - 1 + r;
        int gx = x0 - 1 + cc;
        __half v;
        if (gy < 0 || gx < 0) {
            v = __ushort_as_half(0);
        } else {
            if (gy == 256) gy = 254;      // reflect bottom
            if (gx == 256) gx = 254;      // reflect right
            v = in[gy * 256 + gx];
        }
        sm[r][cc] = v;
    }
    __syncthreads();

    float w[9];
    #pragma unroll
    for (int t9 = 0; t9 < 9; t9++) w[t9] = dw_w[c * 9 + t9];
    const float invs = gamma[c] * rsqrtf(var[c] + 1e-5f);
    const float bias = beta[c] - mean[c] * invs;

    // ---- each thread computes 4 contiguous outputs ----
    const int ly = tid >> 5;            // 0..7
    const int lx = (tid & 31) * 4;      // 0..124
    float o[4] = {0.f, 0.f, 0.f, 0.f};
    #pragma unroll
    for (int di = 0; di < 3; di++) {
        float rowv[6];
        #pragma unroll
        for (int j = 0; j < 6; j++) rowv[j] = __half2float(sm[ly + di][lx + j]);
        #pragma unroll
        for (int dj = 0; dj < 3; dj++) {
            const float wv = w[di * 3 + dj];
            o[0] += wv * rowv[dj];
            o[1] += wv * rowv[dj + 1];
            o[2] += wv * rowv[dj + 2];
            o[3] += wv * rowv[dj + 3];
        }
    }
    uint2 res;
    __half2* rp = reinterpret_cast<__half2*>(&res);
    rp[0] = __floats2half2_rn(o[0] * invs + bias, o[1] * invs + bias);
    rp[1] = __floats2half2_rn(o[2] * invs + bias, o[3] * invs + bias);
    *reinterpret_cast<uint2*>(yh + ((size_t)b * CCH + c) * HW
                              + (size_t)(y0 + ly) * 256 + x0 + lx) = res;
}

// ---------------------------------------------------------------------------
extern "C" void kernel_launch(void* const* d_in, const int* in_sizes, int n_in,
                              void* d_out, int out_size) {
    const float* x          = (const float*)d_in[0];
    const float* qkv_w      = (const float*)d_in[1];
    const float* bias_table = (const float*)d_in[2];
    const float* dw_w       = (const float*)d_in[3];
    const float* bn_gamma   = (const float*)d_in[4];
    const float* bn_beta    = (const float*)d_in[5];
    const float* bn_mean    = (const float*)d_in[6];
    const float* bn_var     = (const float*)d_in[7];
    const float* pw_w       = (const float*)d_in[8];
    float* out = (float*)d_out;

    __half* qkv; cudaGetSymbolAddress((void**)&qkv, g_qkv);
    __half* att; cudaGetSymbolAddress((void**)&att, g_att);
    __half *xh, *yh, *wq, *wp;
    cudaGetSymbolAddress((void**)&xh, g_xh);
    cudaGetSymbolAddress((void**)&yh, g_yh);
    cudaGetSymbolAddress((void**)&wq, g_wq);
    cudaGetSymbolAddress((void**)&wp, g_wp);

    cudaFuncSetAttribute(mma_gemm<0>, cudaFuncAttributeMaxDynamicSharedMemorySize, SM_TOT);
    cudaFuncSetAttribute(mma_gemm<1>, cudaFuncAttributeMaxDynamicSharedMemorySize, SM_TOT);

    // 0) fp16 conversions
    {
        size_t n4 = ((size_t)NB * CCH * HW) / 4;
        cvt_f16<<<(unsigned)((n4 + 255) / 256), 256>>>(x, xh, n4);
        cvt_f16<<<(768 * 256 / 4 + 255) / 256, 256>>>(qkv_w, wq, 768 * 256 / 4);
        cvt_f16<<<(256 * 256 / 4 + 255) / 256, 256>>>(pw_w, wp, 256 * 256 / 4);
    }

    // 1) qkv GEMM -> fp16 window layout
    mma_gemm<1><<<dim3(768 / 128, HW / 128, NB), 256, SM_TOT>>>(wq, xh, qkv, 768);

    // 2) smem-staged tensor-core windowed attention + bias + softmax + residual
    attn_mma<<<dim3(2048, 4), 256>>>(qkv, xh, bias_table, att);

    // 3) reflect-pad + depthwise 3x3 + BN -> fp16 (smem-halo tiled)
    dwbn_kernel<<<dim3(2, 32, NB * CCH), 256>>>(att, dw_w, bn_gamma, bn_beta,
                                                bn_mean, bn_var, yh);

    // 4) pointwise GEMM -> d_out (fp32 channel-major)
    mma_gemm<0><<<dim3(256 / 128, HW / 128, NB), 256, SM_TOT>>>(wp, yh, out, 256);
}

// round 16
// speedup vs baseline: 1.4523x; 1.4523x over previous
#include <cuda_runtime.h>
#include <cuda_fp16.h>
#include <cstdint>

#define HW 65536       // 256*256
#define CCH 256
#define NB 2

// ---------------------------------------------------------------------------
// Scratch (device globals — no allocations allowed)
// ---------------------------------------------------------------------------
__device__ __half g_qkv[(size_t)NB * 768 * HW];   // fp16, window layout [win][part][head][d][tok]
__device__ __half g_att[(size_t)NB * CCH * HW];   // fp16 attention+residual, channel-major
__device__ __half g_xh [(size_t)NB * CCH * HW];
__device__ __half g_yh [(size_t)NB * CCH * HW];
__device__ __half g_wq [768 * 256];
__device__ __half g_wp [256 * 256];

// ---------------------------------------------------------------------------
// PTX helpers (plain sm_80+ PTX)
// ---------------------------------------------------------------------------
__device__ __forceinline__ uint32_t smem_to_u32(const void* p) {
    uint32_t a;
    asm("{ .reg .u64 t; cvta.to.shared.u64 t, %1; cvt.u32.u64 %0, t; }" : "=r"(a) : "l"(p));
    return a;
}
__device__ __forceinline__ void ldsm_x4(uint32_t (&r)[4], uint32_t addr) {
    asm volatile("ldmatrix.sync.aligned.m8n8.x4.shared.b16 {%0,%1,%2,%3}, [%4];"
                 : "=r"(r[0]), "=r"(r[1]), "=r"(r[2]), "=r"(r[3]) : "r"(addr));
}
__device__ __forceinline__ void ldsm_x4_t(uint32_t (&r)[4], uint32_t addr) {
    asm volatile("ldmatrix.sync.aligned.m8n8.x4.trans.shared.b16 {%0,%1,%2,%3}, [%4];"
                 : "=r"(r[0]), "=r"(r[1]), "=r"(r[2]), "=r"(r[3]) : "r"(addr));
}
__device__ __forceinline__ void ldsm_x2_t(uint32_t (&r)[2], uint32_t addr) {
    asm volatile("ldmatrix.sync.aligned.m8n8.x2.trans.shared.b16 {%0,%1}, [%2];"
                 : "=r"(r[0]), "=r"(r[1]) : "r"(addr));
}
__device__ __forceinline__ void mma_f16(float (&c)[4], const uint32_t (&a)[4],
                                        const uint32_t* b) {
    asm volatile("mma.sync.aligned.m16n8k16.row.col.f32.f16.f16.f32 "
                 "{%0,%1,%2,%3}, {%4,%5,%6,%7}, {%8,%9}, {%0,%1,%2,%3};"
                 : "+f"(c[0]), "+f"(c[1]), "+f"(c[2]), "+f"(c[3])
                 : "r"(a[0]), "r"(a[1]), "r"(a[2]), "r"(a[3]), "r"(b[0]), "r"(b[1]));
}
__device__ __forceinline__ void cp_async16(uint32_t sm, const void* g) {
    asm volatile("cp.async.cg.shared.global [%0], [%1], 16;" :: "r"(sm), "l"(g));
}
__device__ __forceinline__ uint32_t pack_f16x2(float lo, float hi) {
    uint32_t r;
    asm("cvt.rn.f16x2.f32 %0, %1, %2;" : "=r"(r) : "f"(hi), "f"(lo));
    return r;
}

// ---------------------------------------------------------------------------
// fp32 -> fp16 convert (vectorized by 4)
// ---------------------------------------------------------------------------
__global__ __launch_bounds__(256) void cvt_f16(const float* __restrict__ in,
                                               __half* __restrict__ out, size_t n4) {
    size_t i = (size_t)blockIdx.x * blockDim.x + threadIdx.x;
    if (i >= n4) return;
    float4 v = reinterpret_cast<const float4*>(in)[i];
    reinterpret_cast<__half2*>(out)[i * 2]     = __floats2half2_rn(v.x, v.y);
    reinterpret_cast<__half2*>(out)[i * 2 + 1] = __floats2half2_rn(v.z, v.w);
}

// ---------------------------------------------------------------------------
// cp.async pipelined fp16 tensor-core GEMM with smem-resident A (R13 config).
// BM=128, BN=128, BK=32; 256 threads (8 warps, 2x4), warp tile 64x32.
// MODE 0: write fp32 channel-major.  MODE 1: write fp16 window layout.
// ---------------------------------------------------------------------------
#define SA_STRIDE 528      // 256 halfs (512B) + 16B pad  (132 words ≡ 4 mod 32)
#define SB_STRIDE 272      // 128 halfs (256B) padded
#define SA_OFF 0
#define SB_OFF 67584       // 128*528
#define BSTAGE 8704        // 32*272
#define SM_TOT (67584 + 4 * BSTAGE)   // 102400

template<int MODE>
__global__ __launch_bounds__(256, 2) void mma_gemm(const __half* __restrict__ Wm,
                                                   const __half* __restrict__ X,
                                                   void* __restrict__ Yv, int Mtot) {
    extern __shared__ __align__(128) char smem[];
    const int tid  = threadIdx.x;
    const int wid  = tid >> 5;
    const int lane = tid & 31;
    const int g    = lane >> 2;
    const int t4   = lane & 3;

    const int oBase = blockIdx.x * 128;
    const int sBase = blockIdx.y * 128;
    const int b     = blockIdx.z;
    const __half* Xb = X + (size_t)b * CCH * HW;

    const int wm = (wid >> 2) * 64;
    const int wn = (wid & 3) * 32;
    const uint32_t sb = smem_to_u32(smem);

    const int bk_ = tid >> 4, bq_ = tid & 15;

    float acc[4][4][4];
    #pragma unroll
    for (int mi = 0; mi < 4; mi++)
        #pragma unroll
        for (int ni = 0; ni < 4; ni++)
            #pragma unroll
            for (int q = 0; q < 4; q++) acc[mi][ni][q] = 0.f;

    // ---- prologue: stage the FULL A slab (128 x 256 halfs) once ----
    {
        #pragma unroll
        for (int p = 0; p < 16; p++) {
            int i = tid + p * 256;           // 0..4095
            int r = i >> 5, c = i & 31;
            cp_async16(sb + SA_OFF + r * SA_STRIDE + c * 16,
                       Wm + (size_t)(oBase + r) * 256 + c * 8);
        }
        asm volatile("cp.async.commit_group;");
    }

    auto issueB = [&](int chunk) {
        const int kc = chunk * 32;
        const uint32_t st = sb + SB_OFF + (chunk & 3) * BSTAGE;
        #pragma unroll
        for (int p = 0; p < 2; p++) {
            int k = bk_ + p * 16;
            cp_async16(st + k * SB_STRIDE + bq_ * 16,
                       Xb + (size_t)(kc + k) * HW + sBase + bq_ * 8);
        }
        asm volatile("cp.async.commit_group;");
    };

    const int bquad = lane >> 3, bj = lane & 7;
    const int bkrow = (bquad & 1) * 8 + bj;
    const int bcol8 = (bquad >> 1) * 8;

    issueB(0); issueB(1); issueB(2);
    #pragma unroll
    for (int chunk = 0; chunk < 8; chunk++) {
        if (chunk < 6) {
            asm volatile("cp.async.wait_group 2;");
        } else if (chunk == 6) {
            asm volatile("cp.async.wait_group 1;");
        } else {
            asm volatile("cp.async.wait_group 0;");
        }
        __syncthreads();
        if (chunk < 5) issueB(chunk + 3);

        const uint32_t smb = sb + SB_OFF + (chunk & 3) * BSTAGE;
        const int ar    = wm + (lane & 15);
        const int acolq = (lane >> 4) * 8;

        #pragma unroll
        for (int ks = 0; ks < 2; ks++) {
            uint32_t a[4][4];
            const int acol = chunk * 32 + ks * 16 + acolq;
            #pragma unroll
            for (int mi = 0; mi < 4; mi++)
                ldsm_x4(a[mi], sb + SA_OFF + (ar + mi * 16) * SA_STRIDE + acol * 2);
            uint32_t bfr[2][4];
            #pragma unroll
            for (int ni2 = 0; ni2 < 2; ni2++)
                ldsm_x4_t(bfr[ni2], smb + (ks * 16 + bkrow) * SB_STRIDE
                                     + (wn + ni2 * 16 + bcol8) * 2);
            #pragma unroll
            for (int mi = 0; mi < 4; mi++)
                #pragma unroll
                for (int ni = 0; ni < 4; ni++)
                    mma_f16(acc[mi][ni], a[mi], &bfr[ni >> 1][(ni & 1) * 2]);
        }
    }

    if (MODE == 0) {
        float* Yb = (float*)Yv + (size_t)b * Mtot * HW;
        #pragma unroll
        for (int mi = 0; mi < 4; mi++) {
            #pragma unroll
            for (int ni = 0; ni < 4; ni++) {
                float* dst0 = Yb + (size_t)(oBase + wm + mi * 16 + g) * HW
                                 + sBase + wn + ni * 8 + t4 * 2;
                *reinterpret_cast<float2*>(dst0) = make_float2(acc[mi][ni][0], acc[mi][ni][1]);
                *reinterpret_cast<float2*>(dst0 + 8 * HW) = make_float2(acc[mi][ni][2], acc[mi][ni][3]);
            }
        }
    } else {
        __half* U = (__half*)Yv;
        #pragma unroll
        for (int mi = 0; mi < 4; mi++) {
            #pragma unroll
            for (int ni = 0; ni < 4; ni++) {
                const int o0   = oBase + wm + mi * 16 + g;
                const int part = o0 >> 8;
                const int head = (o0 >> 4) & 15;
                const int dd   = o0 & 15;
                const int s0   = sBase + wn + ni * 8 + t4 * 2;
                const int y    = s0 >> 8, xx = s0 & 255;
                const int win  = b * 1024 + (y >> 3) * 32 + (xx >> 3);
                const int tok  = (y & 7) * 8 + (xx & 7);
                const size_t base = ((size_t)(win * 3 + part) * 16 + head) * 1024 + tok;
                *reinterpret_cast<__half2*>(U + base + (size_t)dd * 64) =
                    __floats2half2_rn(acc[mi][ni][0], acc[mi][ni][1]);
                *reinterpret_cast<__half2*>(U + base + (size_t)(dd + 8) * 64) =
                    __floats2half2_rn(acc[mi][ni][2], acc[mi][ni][3]);
            }
        }
    }
}

// ---------------------------------------------------------------------------
// Tensor-core window attention (fp16), smem-staged (R9 config).
// ---------------------------------------------------------------------------
#define QROW 144
#define SEGSZ 2304

__global__ __launch_bounds__(256) void attn_mma(const __half* __restrict__ qkvH,
                                                const __half* __restrict__ xh,
                                                const float* __restrict__ bias_table,
                                                __half* __restrict__ att) {
    const int win = blockIdx.x;
    const int hg  = blockIdx.y;
    const int tid = threadIdx.x;
    const int w    = tid >> 5;
    const int lane = tid & 31;
    const int hl   = w >> 1;
    const int wsub = w & 1;
    const int g = lane >> 2, t = lane & 3;

    __shared__ __align__(16) char qs[12 * SEGSZ];
    __shared__ float  bs4[4][225];
    __shared__ __half obuf[4][16][80];

    const uint32_t qs_b = smem_to_u32(qs);

    #pragma unroll
    for (int p = 0; p < 6; p++) {
        int i = tid + p * 256;
        int seg = i >> 7;
        int c   = i & 127;
        int part = seg >> 2, hl2 = seg & 3;
        const __half* src = qkvH + ((size_t)(win * 3 + part) * 16 + hg * 4 + hl2) * 1024 + c * 8;
        cp_async16(qs_b + seg * SEGSZ + (c >> 3) * QROW + (c & 7) * 16, src);
    }
    asm volatile("cp.async.commit_group;");
    for (int i = tid; i < 900; i += 256)
        bs4[i / 225][i % 225] = bias_table[(i % 225) * 16 + hg * 4 + i / 225];
    asm volatile("cp.async.wait_group 0;");
    __syncthreads();

    const uint32_t qbase = qs_b + hl * SEGSZ;
    const uint32_t kbase = qs_b + (4 + hl) * SEGSZ;
    const uint32_t* Vs32 = (const uint32_t*)(qs + (8 + hl) * SEGSZ);

    uint32_t afr[2][4];
    {
        const int quad = lane >> 3, j = lane & 7;
        const int krow = ((quad >= 2) ? 8 : 0) + j;
        const int mcolo = (quad & 1) ? 16 : 0;
        #pragma unroll
        for (int mi = 0; mi < 2; mi++) {
            const int m0 = wsub * 32 + mi * 16;
            ldsm_x4_t(afr[mi], qbase + krow * QROW + m0 * 2 + mcolo);
        }
    }
    uint32_t bfr[8][2];
    #pragma unroll
    for (int ni = 0; ni < 8; ni++)
        ldsm_x2_t(bfr[ni], kbase + (lane & 15) * QROW + ni * 16);

    float C[2][8][4];
    #pragma unroll
    for (int mi = 0; mi < 2; mi++)
        #pragma unroll
        for (int ni = 0; ni < 8; ni++) {
            C[mi][ni][0] = C[mi][ni][1] = C[mi][ni][2] = C[mi][ni][3] = 0.f;
            mma_f16(C[mi][ni], afr[mi], bfr[ni]);
        }

    #pragma unroll
    for (int mi = 0; mi < 2; mi++) {
        const int yl0 = wsub * 4 + mi * 2;
        float m0 = -1e30f, m1 = -1e30f;
        #pragma unroll
        for (int ni = 0; ni < 8; ni++) {
            const int cb0 = g - t * 2 + 7;
            C[mi][ni][0] = C[mi][ni][0] * 0.25f + bs4[hl][(yl0 - ni + 7) * 15 + cb0];
            C[mi][ni][1] = C[mi][ni][1] * 0.25f + bs4[hl][(yl0 - ni + 7) * 15 + cb0 - 1];
            C[mi][ni][2] = C[mi][ni][2] * 0.25f + bs4[hl][(yl0 + 1 - ni + 7) * 15 + cb0];
            C[mi][ni][3] = C[mi][ni][3] * 0.25f + bs4[hl][(yl0 + 1 - ni + 7) * 15 + cb0 - 1];
            m0 = fmaxf(m0, fmaxf(C[mi][ni][0], C[mi][ni][1]));
            m1 = fmaxf(m1, fmaxf(C[mi][ni][2], C[mi][ni][3]));
        }
        m0 = fmaxf(m0, __shfl_xor_sync(0xffffffffu, m0, 1));
        m0 = fmaxf(m0, __shfl_xor_sync(0xffffffffu, m0, 2));
        m1 = fmaxf(m1, __shfl_xor_sync(0xffffffffu, m1, 1));
        m1 = fmaxf(m1, __shfl_xor_sync(0xffffffffu, m1, 2));
        float s0 = 0.f, s1 = 0.f;
        #pragma unroll
        for (int ni = 0; ni < 8; ni++) {
            C[mi][ni][0] = __expf(C[mi][ni][0] - m0);
            C[mi][ni][1] = __expf(C[mi][ni][1] - m0);
            C[mi][ni][2] = __expf(C[mi][ni][2] - m1);
            C[mi][ni][3] = __expf(C[mi][ni][3] - m1);
            s0 += C[mi][ni][0] + C[mi][ni][1];
            s1 += C[mi][ni][2] + C[mi][ni][3];
        }
        s0 += __shfl_xor_sync(0xffffffffu, s0, 1);
        s0 += __shfl_xor_sync(0xffffffffu, s0, 2);
        s1 += __shfl_xor_sync(0xffffffffu, s1, 1);
        s1 += __shfl_xor_sync(0xffffffffu, s1, 2);
        const float iv0 = 1.f / s0, iv1 = 1.f / s1;
        #pragma unroll
        for (int ni = 0; ni < 8; ni++) {
            C[mi][ni][0] *= iv0; C[mi][ni][1] *= iv0;
            C[mi][ni][2] *= iv1; C[mi][ni][3] *= iv1;
        }
    }

    float O[2][2][4];
    #pragma unroll
    for (int mi = 0; mi < 2; mi++)
        #pragma unroll
        for (int nd = 0; nd < 2; nd++)
            O[mi][nd][0] = O[mi][nd][1] = O[mi][nd][2] = O[mi][nd][3] = 0.f;

    #pragma unroll
    for (int kk = 0; kk < 4; kk++) {
        uint32_t vfr[2][2];
        #pragma unroll
        for (int nd = 0; nd < 2; nd++)
            #pragma unroll
            for (int r = 0; r < 2; r++)
                vfr[nd][r] = Vs32[(nd * 8 + g) * 36 + kk * 8 + t + r * 4];
        #pragma unroll
        for (int mi = 0; mi < 2; mi++) {
            uint32_t pfr[4];
            #pragma unroll
            for (int r = 0; r < 4; r++) {
                const int ni = 2 * kk + (r >> 1);
                pfr[r] = pack_f16x2(C[mi][ni][(r & 1) * 2], C[mi][ni][(r & 1) * 2 + 1]);
            }
            #pragma unroll
            for (int nd = 0; nd < 2; nd++)
                mma_f16(O[mi][nd], pfr, vfr[nd]);
        }
    }

    #pragma unroll
    for (int mi = 0; mi < 2; mi++) {
        const int m = wsub * 32 + mi * 16 + g;
        #pragma unroll
        for (int nd = 0; nd < 2; nd++) {
            const int d0 = nd * 8 + t * 2;
            obuf[hl][d0    ][m]     = __float2half(O[mi][nd][0]);
            obuf[hl][d0 + 1][m]     = __float2half(O[mi][nd][1]);
            obuf[hl][d0    ][m + 8] = __float2half(O[mi][nd][2]);
            obuf[hl][d0 + 1][m + 8] = __float2half(O[mi][nd][3]);
        }
    }
    __syncthreads();

    const int bW = win >> 10, loc = win & 1023;
    const int wy = loc >> 5, wx = loc & 31;
    #pragma unroll
    for (int p = 0; p < 2; p++) {
        const int i   = tid + p * 256;
        const int hl2 = i >> 7;
        const int d   = (i >> 3) & 15;
        const int row = i & 7;
        const size_t off = ((size_t)bW * 256 + (hg * 4 + hl2) * 16 + d) * HW
                         + (size_t)(wy * 8 + row) * 256 + wx * 8;
        uint4 xv = *reinterpret_cast<const uint4*>(xh + off);
        const __half2* ob = reinterpret_cast<const __half2*>(&obuf[hl2][d][row * 8]);
        __half2* xp = reinterpret_cast<__half2*>(&xv);
        uint4 res;
        __half2* rp = reinterpret_cast<__half2*>(&res);
        #pragma unroll
        for (int q = 0; q < 4; q++) rp[q] = __hadd2(ob[q], xp[q]);
        *reinterpret_cast<uint4*>(att + off) = res;
    }
}

// ---------------------------------------------------------------------------
// reflect-pad -> depthwise 3x3 -> BN -> fp16  (2 outputs per thread)
// grid: (4, 32, NB*CCH), block (32, 8); thread covers x = 2*(bx*32+tx), +1
// ---------------------------------------------------------------------------
__global__ __launch_bounds__(256) void dwbn_kernel(const __half* __restrict__ att,
                                                   const float* __restrict__ dw_w,
                                                   const float* __restrict__ gamma,
                                                   const float* __restrict__ beta,
                                                   const float* __restrict__ mean,
                                                   const float* __restrict__ var,
                                                   __half* __restrict__ yh) {
    const int c  = blockIdx.z & 255;
    const int b  = blockIdx.z >> 8;
    const int ox = (blockIdx.x * 32 + threadIdx.x) * 2;
    const int oy = blockIdx.y * 8 + threadIdx.y;

    const __half* in = att + ((size_t)b * CCH + c) * HW;
    float w[9];
    #pragma unroll
    for (int tt = 0; tt < 9; tt++) w[tt] = dw_w[c * 9 + tt];

    float a0 = 0.f, a1 = 0.f;
    #pragma unroll
    for (int di = 0; di < 3; di++) {
        int r = oy + di - 1;
        if (r < 0) continue;
        if (r == 256) r = 254;
        const __half* row = in + r * 256;
        float v[4];
        #pragma unroll
        for (int j = 0; j < 4; j++) {
            int cc = ox + j - 1;
            if (cc < 0) { v[j] = 0.f; continue; }
            if (cc == 256) cc = 254;
            v[j] = __half2float(__ldg(&row[cc]));
        }
        #pragma unroll
        for (int dj = 0; dj < 3; dj++) {
            const float wv = w[di * 3 + dj];
            a0 += wv * v[dj];
            a1 += wv * v[dj + 1];
        }
    }
    const float invs = gamma[c] * rsqrtf(var[c] + 1e-5f);
    const float bias = beta[c] - mean[c] * invs;
    __half2 res = __floats2half2_rn(a0 * invs + bias, a1 * invs + bias);
    *reinterpret_cast<__half2*>(yh + ((size_t)b * CCH + c) * HW + oy * 256 + ox) = res;
}

// ---------------------------------------------------------------------------
extern "C" void kernel_launch(void* const* d_in, const int* in_sizes, int n_in,
                              void* d_out, int out_size) {
    const float* x          = (const float*)d_in[0];
    const float* qkv_w      = (const float*)d_in[1];
    const float* bias_table = (const float*)d_in[2];
    const float* dw_w       = (const float*)d_in[3];
    const float* bn_gamma   = (const float*)d_in[4];
    const float* bn_beta    = (const float*)d_in[5];
    const float* bn_mean    = (const float*)d_in[6];
    const float* bn_var     = (const float*)d_in[7];
    const float* pw_w       = (const float*)d_in[8];
    float* out = (float*)d_out;

    __half* qkv; cudaGetSymbolAddress((void**)&qkv, g_qkv);
    __half* att; cudaGetSymbolAddress((void**)&att, g_att);
    __half *xh, *yh, *wq, *wp;
    cudaGetSymbolAddress((void**)&xh, g_xh);
    cudaGetSymbolAddress((void**)&yh, g_yh);
    cudaGetSymbolAddress((void**)&wq, g_wq);
    cudaGetSymbolAddress((void**)&wp, g_wp);

    cudaFuncSetAttribute(mma_gemm<0>, cudaFuncAttributeMaxDynamicSharedMemorySize, SM_TOT);
    cudaFuncSetAttribute(mma_gemm<1>, cudaFuncAttributeMaxDynamicSharedMemorySize, SM_TOT);

    // 0) fp16 conversions
    {
        size_t n4 = ((size_t)NB * CCH * HW) / 4;
        cvt_f16<<<(unsigned)((n4 + 255) / 256), 256>>>(x, xh, n4);
        cvt_f16<<<(768 * 256 / 4 + 255) / 256, 256>>>(qkv_w, wq, 768 * 256 / 4);
        cvt_f16<<<(256 * 256 / 4 + 255) / 256, 256>>>(pw_w, wp, 256 * 256 / 4);
    }

    // 1) qkv GEMM -> fp16 window layout
    mma_gemm<1><<<dim3(768 / 128, HW / 128, NB), 256, SM_TOT>>>(wq, xh, qkv, 768);

    // 2) smem-staged tensor-core windowed attention + bias + softmax + residual
    attn_mma<<<dim3(2048, 4), 256>>>(qkv, xh, bias_table, att);

    // 3) reflect-pad + depthwise 3x3 + BN -> fp16 (2 outputs/thread)
    dwbn_kernel<<<dim3(4, 32, NB * CCH), dim3(32, 8)>>>(att, dw_w, bn_gamma, bn_beta,
                                                        bn_mean, bn_var, yh);

    // 4) pointwise GEMM -> d_out (fp32 channel-major)
    mma_gemm<0><<<dim3(256 / 128, HW / 128, NB), 256, SM_TOT>>>(wp, yh, out, 256);
}

// round 17
// speedup vs baseline: 1.4571x; 1.0033x over previous
#include <cuda_runtime.h>
#include <cuda_fp16.h>
#include <cstdint>

#define HW 65536       // 256*256
#define CCH 256
#define NB 2

// ---------------------------------------------------------------------------
// Scratch (device globals — no allocations allowed)
// ---------------------------------------------------------------------------
__device__ __half g_qkv[(size_t)NB * 768 * HW];   // fp16, window layout [win][part][head][d][tok]
__device__ __half g_att[(size_t)NB * CCH * HW];   // fp16 attention+residual, channel-major
__device__ __half g_xh [(size_t)NB * CCH * HW];
__device__ __half g_yh [(size_t)NB * CCH * HW];
__device__ __half g_wq [768 * 256];
__device__ __half g_wp [256 * 256];

// ---------------------------------------------------------------------------
// PTX helpers (plain sm_80+ PTX)
// ---------------------------------------------------------------------------
__device__ __forceinline__ uint32_t smem_to_u32(const void* p) {
    uint32_t a;
    asm("{ .reg .u64 t; cvta.to.shared.u64 t, %1; cvt.u32.u64 %0, t; }" : "=r"(a) : "l"(p));
    return a;
}
__device__ __forceinline__ void ldsm_x4(uint32_t (&r)[4], uint32_t addr) {
    asm volatile("ldmatrix.sync.aligned.m8n8.x4.shared.b16 {%0,%1,%2,%3}, [%4];"
                 : "=r"(r[0]), "=r"(r[1]), "=r"(r[2]), "=r"(r[3]) : "r"(addr));
}
__device__ __forceinline__ void ldsm_x4_t(uint32_t (&r)[4], uint32_t addr) {
    asm volatile("ldmatrix.sync.aligned.m8n8.x4.trans.shared.b16 {%0,%1,%2,%3}, [%4];"
                 : "=r"(r[0]), "=r"(r[1]), "=r"(r[2]), "=r"(r[3]) : "r"(addr));
}
__device__ __forceinline__ void ldsm_x2_t(uint32_t (&r)[2], uint32_t addr) {
    asm volatile("ldmatrix.sync.aligned.m8n8.x2.trans.shared.b16 {%0,%1}, [%2];"
                 : "=r"(r[0]), "=r"(r[1]) : "r"(addr));
}
__device__ __forceinline__ void mma_f16(float (&c)[4], const uint32_t (&a)[4],
                                        const uint32_t* b) {
    asm volatile("mma.sync.aligned.m16n8k16.row.col.f32.f16.f16.f32 "
                 "{%0,%1,%2,%3}, {%4,%5,%6,%7}, {%8,%9}, {%0,%1,%2,%3};"
                 : "+f"(c[0]), "+f"(c[1]), "+f"(c[2]), "+f"(c[3])
                 : "r"(a[0]), "r"(a[1]), "r"(a[2]), "r"(a[3]), "r"(b[0]), "r"(b[1]));
}
__device__ __forceinline__ void cp_async16(uint32_t sm, const void* g) {
    asm volatile("cp.async.cg.shared.global [%0], [%1], 16;" :: "r"(sm), "l"(g));
}
__device__ __forceinline__ uint32_t pack_f16x2(float lo, float hi) {
    uint32_t r;
    asm("cvt.rn.f16x2.f32 %0, %1, %2;" : "=r"(r) : "f"(hi), "f"(lo));
    return r;
}

// ---------------------------------------------------------------------------
// fp32 -> fp16 convert (vectorized by 4)
// ---------------------------------------------------------------------------
__global__ __launch_bounds__(256) void cvt_f16(const float* __restrict__ in,
                                               __half* __restrict__ out, size_t n4) {
    size_t i = (size_t)blockIdx.x * blockDim.x + threadIdx.x;
    if (i >= n4) return;
    float4 v = reinterpret_cast<const float4*>(in)[i];
    reinterpret_cast<__half2*>(out)[i * 2]     = __floats2half2_rn(v.x, v.y);
    reinterpret_cast<__half2*>(out)[i * 2 + 1] = __floats2half2_rn(v.z, v.w);
}

// ---------------------------------------------------------------------------
// cp.async pipelined fp16 tensor-core GEMM with smem-resident A (R13 config).
// BM=128, BN=128, BK=32; 256 threads (8 warps, 2x4), warp tile 64x32.
// MODE 0: write fp32 channel-major.  MODE 1: write fp16 window layout.
// ---------------------------------------------------------------------------
#define SA_STRIDE 528      // 256 halfs (512B) + 16B pad  (132 words ≡ 4 mod 32)
#define SB_STRIDE 272      // 128 halfs (256B) padded
#define SA_OFF 0
#define SB_OFF 67584       // 128*528
#define BSTAGE 8704        // 32*272
#define SM_TOT (67584 + 4 * BSTAGE)   // 102400

template<int MODE>
__global__ __launch_bounds__(256, 2) void mma_gemm(const __half* __restrict__ Wm,
                                                   const __half* __restrict__ X,
                                                   void* __restrict__ Yv, int Mtot) {
    extern __shared__ __align__(128) char smem[];
    const int tid  = threadIdx.x;
    const int wid  = tid >> 5;
    const int lane = tid & 31;
    const int g    = lane >> 2;
    const int t4   = lane & 3;

    const int oBase = blockIdx.x * 128;
    const int sBase = blockIdx.y * 128;
    const int b     = blockIdx.z;
    const __half* Xb = X + (size_t)b * CCH * HW;

    const int wm = (wid >> 2) * 64;
    const int wn = (wid & 3) * 32;
    const uint32_t sb = smem_to_u32(smem);

    const int bk_ = tid >> 4, bq_ = tid & 15;

    float acc[4][4][4];
    #pragma unroll
    for (int mi = 0; mi < 4; mi++)
        #pragma unroll
        for (int ni = 0; ni < 4; ni++)
            #pragma unroll
            for (int q = 0; q < 4; q++) acc[mi][ni][q] = 0.f;

    // ---- prologue: stage the FULL A slab (128 x 256 halfs) once ----
    {
        #pragma unroll
        for (int p = 0; p < 16; p++) {
            int i = tid + p * 256;           // 0..4095
            int r = i >> 5, c = i & 31;
            cp_async16(sb + SA_OFF + r * SA_STRIDE + c * 16,
                       Wm + (size_t)(oBase + r) * 256 + c * 8);
        }
        asm volatile("cp.async.commit_group;");
    }

    auto issueB = [&](int chunk) {
        const int kc = chunk * 32;
        const uint32_t st = sb + SB_OFF + (chunk & 3) * BSTAGE;
        #pragma unroll
        for (int p = 0; p < 2; p++) {
            int k = bk_ + p * 16;
            cp_async16(st + k * SB_STRIDE + bq_ * 16,
                       Xb + (size_t)(kc + k) * HW + sBase + bq_ * 8);
        }
        asm volatile("cp.async.commit_group;");
    };

    const int bquad = lane >> 3, bj = lane & 7;
    const int bkrow = (bquad & 1) * 8 + bj;
    const int bcol8 = (bquad >> 1) * 8;

    issueB(0); issueB(1); issueB(2);
    #pragma unroll
    for (int chunk = 0; chunk < 8; chunk++) {
        if (chunk < 6) {
            asm volatile("cp.async.wait_group 2;");
        } else if (chunk == 6) {
            asm volatile("cp.async.wait_group 1;");
        } else {
            asm volatile("cp.async.wait_group 0;");
        }
        __syncthreads();
        if (chunk < 5) issueB(chunk + 3);

        const uint32_t smb = sb + SB_OFF + (chunk & 3) * BSTAGE;
        const int ar    = wm + (lane & 15);
        const int acolq = (lane >> 4) * 8;

        #pragma unroll
        for (int ks = 0; ks < 2; ks++) {
            uint32_t a[4][4];
            const int acol = chunk * 32 + ks * 16 + acolq;
            #pragma unroll
            for (int mi = 0; mi < 4; mi++)
                ldsm_x4(a[mi], sb + SA_OFF + (ar + mi * 16) * SA_STRIDE + acol * 2);
            uint32_t bfr[2][4];
            #pragma unroll
            for (int ni2 = 0; ni2 < 2; ni2++)
                ldsm_x4_t(bfr[ni2], smb + (ks * 16 + bkrow) * SB_STRIDE
                                     + (wn + ni2 * 16 + bcol8) * 2);
            #pragma unroll
            for (int mi = 0; mi < 4; mi++)
                #pragma unroll
                for (int ni = 0; ni < 4; ni++)
                    mma_f16(acc[mi][ni], a[mi], &bfr[ni >> 1][(ni & 1) * 2]);
        }
    }

    if (MODE == 0) {
        float* Yb = (float*)Yv + (size_t)b * Mtot * HW;
        #pragma unroll
        for (int mi = 0; mi < 4; mi++) {
            #pragma unroll
            for (int ni = 0; ni < 4; ni++) {
                float* dst0 = Yb + (size_t)(oBase + wm + mi * 16 + g) * HW
                                 + sBase + wn + ni * 8 + t4 * 2;
                *reinterpret_cast<float2*>(dst0) = make_float2(acc[mi][ni][0], acc[mi][ni][1]);
                *reinterpret_cast<float2*>(dst0 + 8 * HW) = make_float2(acc[mi][ni][2], acc[mi][ni][3]);
            }
        }
    } else {
        __half* U = (__half*)Yv;
        #pragma unroll
        for (int mi = 0; mi < 4; mi++) {
            #pragma unroll
            for (int ni = 0; ni < 4; ni++) {
                const int o0   = oBase + wm + mi * 16 + g;
                const int part = o0 >> 8;
                const int head = (o0 >> 4) & 15;
                const int dd   = o0 & 15;
                const int s0   = sBase + wn + ni * 8 + t4 * 2;
                const int y    = s0 >> 8, xx = s0 & 255;
                const int win  = b * 1024 + (y >> 3) * 32 + (xx >> 3);
                const int tok  = (y & 7) * 8 + (xx & 7);
                const size_t base = ((size_t)(win * 3 + part) * 16 + head) * 1024 + tok;
                *reinterpret_cast<__half2*>(U + base + (size_t)dd * 64) =
                    __floats2half2_rn(acc[mi][ni][0], acc[mi][ni][1]);
                *reinterpret_cast<__half2*>(U + base + (size_t)(dd + 8) * 64) =
                    __floats2half2_rn(acc[mi][ni][2], acc[mi][ni][3]);
            }
        }
    }
}

// ---------------------------------------------------------------------------
// Tensor-core window attention (fp16), smem-staged (R9 config).
// ---------------------------------------------------------------------------
#define QROW 144
#define SEGSZ 2304

__global__ __launch_bounds__(256) void attn_mma(const __half* __restrict__ qkvH,
                                                const __half* __restrict__ xh,
                                                const float* __restrict__ bias_table,
                                                __half* __restrict__ att) {
    const int win = blockIdx.x;
    const int hg  = blockIdx.y;
    const int tid = threadIdx.x;
    const int w    = tid >> 5;
    const int lane = tid & 31;
    const int hl   = w >> 1;
    const int wsub = w & 1;
    const int g = lane >> 2, t = lane & 3;

    __shared__ __align__(16) char qs[12 * SEGSZ];
    __shared__ float  bs4[4][225];
    __shared__ __half obuf[4][16][80];

    const uint32_t qs_b = smem_to_u32(qs);

    #pragma unroll
    for (int p = 0; p < 6; p++) {
        int i = tid + p * 256;
        int seg = i >> 7;
        int c   = i & 127;
        int part = seg >> 2, hl2 = seg & 3;
        const __half* src = qkvH + ((size_t)(win * 3 + part) * 16 + hg * 4 + hl2) * 1024 + c * 8;
        cp_async16(qs_b + seg * SEGSZ + (c >> 3) * QROW + (c & 7) * 16, src);
    }
    asm volatile("cp.async.commit_group;");
    for (int i = tid; i < 900; i += 256)
        bs4[i / 225][i % 225] = bias_table[(i % 225) * 16 + hg * 4 + i / 225];
    asm volatile("cp.async.wait_group 0;");
    __syncthreads();

    const uint32_t qbase = qs_b + hl * SEGSZ;
    const uint32_t kbase = qs_b + (4 + hl) * SEGSZ;
    const uint32_t* Vs32 = (const uint32_t*)(qs + (8 + hl) * SEGSZ);

    uint32_t afr[2][4];
    {
        const int quad = lane >> 3, j = lane & 7;
        const int krow = ((quad >= 2) ? 8 : 0) + j;
        const int mcolo = (quad & 1) ? 16 : 0;
        #pragma unroll
        for (int mi = 0; mi < 2; mi++) {
            const int m0 = wsub * 32 + mi * 16;
            ldsm_x4_t(afr[mi], qbase + krow * QROW + m0 * 2 + mcolo);
        }
    }
    uint32_t bfr[8][2];
    #pragma unroll
    for (int ni = 0; ni < 8; ni++)
        ldsm_x2_t(bfr[ni], kbase + (lane & 15) * QROW + ni * 16);

    float C[2][8][4];
    #pragma unroll
    for (int mi = 0; mi < 2; mi++)
        #pragma unroll
        for (int ni = 0; ni < 8; ni++) {
            C[mi][ni][0] = C[mi][ni][1] = C[mi][ni][2] = C[mi][ni][3] = 0.f;
            mma_f16(C[mi][ni], afr[mi], bfr[ni]);
        }

    #pragma unroll
    for (int mi = 0; mi < 2; mi++) {
        const int yl0 = wsub * 4 + mi * 2;
        float m0 = -1e30f, m1 = -1e30f;
        #pragma unroll
        for (int ni = 0; ni < 8; ni++) {
            const int cb0 = g - t * 2 + 7;
            C[mi][ni][0] = C[mi][ni][0] * 0.25f + bs4[hl][(yl0 - ni + 7) * 15 + cb0];
            C[mi][ni][1] = C[mi][ni][1] * 0.25f + bs4[hl][(yl0 - ni + 7) * 15 + cb0 - 1];
            C[mi][ni][2] = C[mi][ni][2] * 0.25f + bs4[hl][(yl0 + 1 - ni + 7) * 15 + cb0];
            C[mi][ni][3] = C[mi][ni][3] * 0.25f + bs4[hl][(yl0 + 1 - ni + 7) * 15 + cb0 - 1];
            m0 = fmaxf(m0, fmaxf(C[mi][ni][0], C[mi][ni][1]));
            m1 = fmaxf(m1, fmaxf(C[mi][ni][2], C[mi][ni][3]));
        }
        m0 = fmaxf(m0, __shfl_xor_sync(0xffffffffu, m0, 1));
        m0 = fmaxf(m0, __shfl_xor_sync(0xffffffffu, m0, 2));
        m1 = fmaxf(m1, __shfl_xor_sync(0xffffffffu, m1, 1));
        m1 = fmaxf(m1, __shfl_xor_sync(0xffffffffu, m1, 2));
        float s0 = 0.f, s1 = 0.f;
        #pragma unroll
        for (int ni = 0; ni < 8; ni++) {
            C[mi][ni][0] = __expf(C[mi][ni][0] - m0);
            C[mi][ni][1] = __expf(C[mi][ni][1] - m0);
            C[mi][ni][2] = __expf(C[mi][ni][2] - m1);
            C[mi][ni][3] = __expf(C[mi][ni][3] - m1);
            s0 += C[mi][ni][0] + C[mi][ni][1];
            s1 += C[mi][ni][2] + C[mi][ni][3];
        }
        s0 += __shfl_xor_sync(0xffffffffu, s0, 1);
        s0 += __shfl_xor_sync(0xffffffffu, s0, 2);
        s1 += __shfl_xor_sync(0xffffffffu, s1, 1);
        s1 += __shfl_xor_sync(0xffffffffu, s1, 2);
        const float iv0 = 1.f / s0, iv1 = 1.f / s1;
        #pragma unroll
        for (int ni = 0; ni < 8; ni++) {
            C[mi][ni][0] *= iv0; C[mi][ni][1] *= iv0;
            C[mi][ni][2] *= iv1; C[mi][ni][3] *= iv1;
        }
    }

    float O[2][2][4];
    #pragma unroll
    for (int mi = 0; mi < 2; mi++)
        #pragma unroll
        for (int nd = 0; nd < 2; nd++)
            O[mi][nd][0] = O[mi][nd][1] = O[mi][nd][2] = O[mi][nd][3] = 0.f;

    #pragma unroll
    for (int kk = 0; kk < 4; kk++) {
        uint32_t vfr[2][2];
        #pragma unroll
        for (int nd = 0; nd < 2; nd++)
            #pragma unroll
            for (int r = 0; r < 2; r++)
                vfr[nd][r] = Vs32[(nd * 8 + g) * 36 + kk * 8 + t + r * 4];
        #pragma unroll
        for (int mi = 0; mi < 2; mi++) {
            uint32_t pfr[4];
            #pragma unroll
            for (int r = 0; r < 4; r++) {
                const int ni = 2 * kk + (r >> 1);
                pfr[r] = pack_f16x2(C[mi][ni][(r & 1) * 2], C[mi][ni][(r & 1) * 2 + 1]);
            }
            #pragma unroll
            for (int nd = 0; nd < 2; nd++)
                mma_f16(O[mi][nd], pfr, vfr[nd]);
        }
    }

    #pragma unroll
    for (int mi = 0; mi < 2; mi++) {
        const int m = wsub * 32 + mi * 16 + g;
        #pragma unroll
        for (int nd = 0; nd < 2; nd++) {
            const int d0 = nd * 8 + t * 2;
            obuf[hl][d0    ][m]     = __float2half(O[mi][nd][0]);
            obuf[hl][d0 + 1][m]     = __float2half(O[mi][nd][1]);
            obuf[hl][d0    ][m + 8] = __float2half(O[mi][nd][2]);
            obuf[hl][d0 + 1][m + 8] = __float2half(O[mi][nd][3]);
        }
    }
    __syncthreads();

    const int bW = win >> 10, loc = win & 1023;
    const int wy = loc >> 5, wx = loc & 31;
    #pragma unroll
    for (int p = 0; p < 2; p++) {
        const int i   = tid + p * 256;
        const int hl2 = i >> 7;
        const int d   = (i >> 3) & 15;
        const int row = i & 7;
        const size_t off = ((size_t)bW * 256 + (hg * 4 + hl2) * 16 + d) * HW
                         + (size_t)(wy * 8 + row) * 256 + wx * 8;
        uint4 xv = *reinterpret_cast<const uint4*>(xh + off);
        const __half2* ob = reinterpret_cast<const __half2*>(&obuf[hl2][d][row * 8]);
        __half2* xp = reinterpret_cast<__half2*>(&xv);
        uint4 res;
        __half2* rp = reinterpret_cast<__half2*>(&res);
        #pragma unroll
        for (int q = 0; q < 4; q++) rp[q] = __hadd2(ob[q], xp[q]);
        *reinterpret_cast<uint4*>(att + off) = res;
    }
}

// ---------------------------------------------------------------------------
// reflect-pad -> depthwise 3x3 -> BN -> fp16  (2 outputs per thread)
// grid: (4, 32, NB*CCH), block (32, 8); thread covers x = 2*(bx*32+tx), +1
// ---------------------------------------------------------------------------
__global__ __launch_bounds__(256) void dwbn_kernel(const __half* __restrict__ att,
                                                   const float* __restrict__ dw_w,
                                                   const float* __restrict__ gamma,
                                                   const float* __restrict__ beta,
                                                   const float* __restrict__ mean,
                                                   const float* __restrict__ var,
                                                   __half* __restrict__ yh) {
    const int c  = blockIdx.z & 255;
    const int b  = blockIdx.z >> 8;
    const int ox = (blockIdx.x * 32 + threadIdx.x) * 2;
    const int oy = blockIdx.y * 8 + threadIdx.y;

    const __half* in = att + ((size_t)b * CCH + c) * HW;
    float w[9];
    #pragma unroll
    for (int tt = 0; tt < 9; tt++) w[tt] = dw_w[c * 9 + tt];

    float a0 = 0.f, a1 = 0.f;
    #pragma unroll
    for (int di = 0; di < 3; di++) {
        int r = oy + di - 1;
        if (r < 0) continue;
        if (r == 256) r = 254;
        const __half* row = in + r * 256;
        float v[4];
        #pragma unroll
        for (int j = 0; j < 4; j++) {
            int cc = ox + j - 1;
            if (cc < 0) { v[j] = 0.f; continue; }
            if (cc == 256) cc = 254;
            v[j] = __half2float(__ldg(&row[cc]));
        }
        #pragma unroll
        for (int dj = 0; dj < 3; dj++) {
            const float wv = w[di * 3 + dj];
            a0 += wv * v[dj];
            a1 += wv * v[dj + 1];
        }
    }
    const float invs = gamma[c] * rsqrtf(var[c] + 1e-5f);
    const float bias = beta[c] - mean[c] * invs;
    __half2 res = __floats2half2_rn(a0 * invs + bias, a1 * invs + bias);
    *reinterpret_cast<__half2*>(yh + ((size_t)b * CCH + c) * HW + oy * 256 + ox) = res;
}

// ---------------------------------------------------------------------------
extern "C" void kernel_launch(void* const* d_in, const int* in_sizes, int n_in,
                              void* d_out, int out_size) {
    const float* x          = (const float*)d_in[0];
    const float* qkv_w      = (const float*)d_in[1];
    const float* bias_table = (const float*)d_in[2];
    const float* dw_w       = (const float*)d_in[3];
    const float* bn_gamma   = (const float*)d_in[4];
    const float* bn_beta    = (const float*)d_in[5];
    const float* bn_mean    = (const float*)d_in[6];
    const float* bn_var     = (const float*)d_in[7];
    const float* pw_w       = (const float*)d_in[8];
    float* out = (float*)d_out;

    __half* qkv; cudaGetSymbolAddress((void**)&qkv, g_qkv);
    __half* att; cudaGetSymbolAddress((void**)&att, g_att);
    __half *xh, *yh, *wq, *wp;
    cudaGetSymbolAddress((void**)&xh, g_xh);
    cudaGetSymbolAddress((void**)&yh, g_yh);
    cudaGetSymbolAddress((void**)&wq, g_wq);
    cudaGetSymbolAddress((void**)&wp, g_wp);

    cudaFuncSetAttribute(mma_gemm<0>, cudaFuncAttributeMaxDynamicSharedMemorySize, SM_TOT);
    cudaFuncSetAttribute(mma_gemm<1>, cudaFuncAttributeMaxDynamicSharedMemorySize, SM_TOT);

    // 0) fp16 conversions
    {
        size_t n4 = ((size_t)NB * CCH * HW) / 4;
        cvt_f16<<<(unsigned)((n4 + 255) / 256), 256>>>(x, xh, n4);
        cvt_f16<<<(768 * 256 / 4 + 255) / 256, 256>>>(qkv_w, wq, 768 * 256 / 4);
        cvt_f16<<<(256 * 256 / 4 + 255) / 256, 256>>>(pw_w, wp, 256 * 256 / 4);
    }

    // 1) qkv GEMM -> fp16 window layout
    mma_gemm<1><<<dim3(768 / 128, HW / 128, NB), 256, SM_TOT>>>(wq, xh, qkv, 768);

    // 2) smem-staged tensor-core windowed attention + bias + softmax + residual
    attn_mma<<<dim3(2048, 4), 256>>>(qkv, xh, bias_table, att);

    // 3) reflect-pad + depthwise 3x3 + BN -> fp16 (2 outputs/thread)
    dwbn_kernel<<<dim3(4, 32, NB * CCH), dim3(32, 8)>>>(att, dw_w, bn_gamma, bn_beta,
                                                        bn_mean, bn_var, yh);

    // 4) pointwise GEMM -> d_out (fp32 channel-major)
    mma_gemm<0><<<dim3(256 / 128, HW / 128, NB), 256, SM_TOT>>>(wp, yh, out, 256);
}